// round 12
// baseline (speedup 1.0000x reference)
#include <cuda_runtime.h>
#include <cuda_fp16.h>
#include <cstdint>

#define NMAX 100000
#define EMAX 1600000
#define DN   64
#define NGR  128

// ---- bit-cast helpers ----
__device__ __forceinline__ float2 h2f(unsigned u) {
    __half2 h = *reinterpret_cast<__half2*>(&u);
    return __half22float2(h);
}
__device__ __forceinline__ unsigned f2h(float a, float b) {
    __half2 h = __floats2half2_rn(a, b);
    return *reinterpret_cast<unsigned*>(&h);
}

// ---------------- device scratch (allocation-free; referenced ONLY in device code) ----------------
__device__ float  g_bufA[NMAX * DN];   // gemm2 output (pool input)
__device__ float  g_bufB[NMAX * DN];   // aggregation target (gather out, gemm in)
__device__ __half g_h16[NMAX * DN];    // fp16 gather source (prep out / gemm1 out)
__device__ int    g_deg[2 * NMAX];     // [0,N): out-deg(src), [N,2N): in-deg(dst)
__device__ float  g_norm[2 * NMAX];    // [0,N): norm_src, [N,2N): norm_dst
__device__ int    g_off[NMAX];         // CSR row offsets (by dst)
__device__ int    g_blk[128];          // scanA block totals (raw)
__device__ int    g_cursor[NMAX];      // CSR fill cursors (seeded = g_off)
__device__ int    g_csr[EMAX];         // CSR: src indices grouped by dst
__device__ float  g_pooled[NGR * DN];
__device__ float  g_counts[NGR];

// ---------------- init ----------------
__global__ void k_zero_init(int N) {
    int i = blockIdx.x * blockDim.x + threadIdx.x;
    if (i < 2 * N)      g_deg[i] = 0;
    if (i < NGR * DN)   g_pooled[i] = 0.f;
    if (i < NGR)        g_counts[i] = 0.f;
}

// ---------------- degrees ----------------
__global__ void k_degree(const int* __restrict__ src, const int* __restrict__ dst, int E, int N) {
    int e = blockIdx.x * blockDim.x + threadIdx.x;
    if (e < E) {
        atomicAdd(&g_deg[src[e]], 1);
        atomicAdd(&g_deg[N + dst[e]], 1);
    }
}

// ---------------- scanA: per-1024-block exclusive scan via warp shuffles ----------------
__global__ void k_scanA(int N) {
    __shared__ int wsum[32];
    int b = blockIdx.x, t = threadIdx.x, i = b * 1024 + t;
    int v = (i < N) ? g_deg[N + i] : 0;
    int x = v;
    #pragma unroll
    for (int o = 1; o < 32; o <<= 1) {
        int y = __shfl_up_sync(0xffffffffu, x, o);
        if ((t & 31) >= o) x += y;
    }
    if ((t & 31) == 31) wsum[t >> 5] = x;
    __syncthreads();
    if (t < 32) {
        int w = wsum[t];
        #pragma unroll
        for (int o = 1; o < 32; o <<= 1) {
            int y = __shfl_up_sync(0xffffffffu, w, o);
            if (t >= o) w += y;
        }
        wsum[t] = w;
    }
    __syncthreads();
    int off = (t >= 32) ? wsum[(t >> 5) - 1] : 0;
    int incl = x + off;
    if (i < N) g_off[i] = incl - v;
    if (t == 1023) g_blk[b] = incl;
}

// ---------------- scanC (thin): finalize offsets, seed cursors, norms ----------------
__global__ void __launch_bounds__(256) k_scanC(int N, int G) {
    __shared__ int sblk[128];
    int t = threadIdx.x;
    int i = blockIdx.x * 256 + t;
    if (t < 128) sblk[t] = (t < G) ? g_blk[t] : 0;
    __syncthreads();
    if (i >= N) return;
    int c = i >> 10;
    int pref = 0;
    for (int b2 = 0; b2 < c; b2++) pref += sblk[b2];
    int o = g_off[i] + pref;
    g_off[i] = o;
    g_cursor[i] = o;
    g_norm[i]     = rsqrtf((float)max(g_deg[i], 1));
    g_norm[N + i] = rsqrtf((float)max(g_deg[N + i], 1));
}

// ---------------- prep: g_h16[n] = h[n] * norm_src[n] (fp16, streaming, 1.6M threads) ----------------
__global__ void k_prep16(const float4* __restrict__ h, int N) {
    int t = blockIdx.x * blockDim.x + threadIdx.x;
    if (t < N * 16) {
        int n = t >> 4;
        float s = g_norm[n];
        float4 v = h[t];
        uint2 o;
        o.x = f2h(v.x * s, v.y * s);
        o.y = f2h(v.z * s, v.w * s);
        reinterpret_cast<uint2*>(g_h16)[t] = o;
    }
}

// ---------------- fill CSR ----------------
__global__ void k_fill(const int* __restrict__ src, const int* __restrict__ dst, int E) {
    int e = blockIdx.x * blockDim.x + threadIdx.x;
    if (e < E) {
        int p = atomicAdd(&g_cursor[dst[e]], 1);
        g_csr[p] = src[e];
    }
}

// ---------------- gather-sum per dst node (fp16 source g_h16, fp32 accum -> g_bufB) ----------------
// 8 threads/node, each handles 8 halves (16B). Unrolled x4, dual accumulators.
__global__ void __launch_bounds__(256) k_gather16(int N) {
    int tid = blockIdx.x * blockDim.x + threadIdx.x;
    int node = tid >> 3;
    if (node >= N) return;
    int q = tid & 7;

    int o = g_off[node];
    int d = g_deg[N + node];
    const uint4* X = reinterpret_cast<const uint4*>(g_h16);

    float2 a0[4], a1[4];
    #pragma unroll
    for (int i = 0; i < 4; i++) {
        a0[i] = make_float2(0.f, 0.f);
        a1[i] = make_float2(0.f, 0.f);
    }

    int j = 0;
    for (; j + 4 <= d; j += 4) {
        int s0 = __ldg(&g_csr[o + j]);
        int s1 = __ldg(&g_csr[o + j + 1]);
        int s2 = __ldg(&g_csr[o + j + 2]);
        int s3 = __ldg(&g_csr[o + j + 3]);
        uint4 r0 = __ldg(&X[(size_t)s0 * 8 + q]);
        uint4 r1 = __ldg(&X[(size_t)s1 * 8 + q]);
        uint4 r2 = __ldg(&X[(size_t)s2 * 8 + q]);
        uint4 r3 = __ldg(&X[(size_t)s3 * 8 + q]);
        float2 f;
        f = h2f(r0.x); a0[0].x += f.x; a0[0].y += f.y;
        f = h2f(r0.y); a0[1].x += f.x; a0[1].y += f.y;
        f = h2f(r0.z); a0[2].x += f.x; a0[2].y += f.y;
        f = h2f(r0.w); a0[3].x += f.x; a0[3].y += f.y;
        f = h2f(r1.x); a1[0].x += f.x; a1[0].y += f.y;
        f = h2f(r1.y); a1[1].x += f.x; a1[1].y += f.y;
        f = h2f(r1.z); a1[2].x += f.x; a1[2].y += f.y;
        f = h2f(r1.w); a1[3].x += f.x; a1[3].y += f.y;
        f = h2f(r2.x); a0[0].x += f.x; a0[0].y += f.y;
        f = h2f(r2.y); a0[1].x += f.x; a0[1].y += f.y;
        f = h2f(r2.z); a0[2].x += f.x; a0[2].y += f.y;
        f = h2f(r2.w); a0[3].x += f.x; a0[3].y += f.y;
        f = h2f(r3.x); a1[0].x += f.x; a1[0].y += f.y;
        f = h2f(r3.y); a1[1].x += f.x; a1[1].y += f.y;
        f = h2f(r3.z); a1[2].x += f.x; a1[2].y += f.y;
        f = h2f(r3.w); a1[3].x += f.x; a1[3].y += f.y;
    }
    for (; j < d; j++) {
        int s = __ldg(&g_csr[o + j]);
        uint4 r = __ldg(&X[(size_t)s * 8 + q]);
        float2 f;
        f = h2f(r.x); a0[0].x += f.x; a0[0].y += f.y;
        f = h2f(r.y); a0[1].x += f.x; a0[1].y += f.y;
        f = h2f(r.z); a0[2].x += f.x; a0[2].y += f.y;
        f = h2f(r.w); a0[3].x += f.x; a0[3].y += f.y;
    }

    float nd = g_norm[N + node];
    float4 lo = make_float4((a0[0].x + a1[0].x) * nd, (a0[0].y + a1[0].y) * nd,
                            (a0[1].x + a1[1].x) * nd, (a0[1].y + a1[1].y) * nd);
    float4 hi = make_float4((a0[2].x + a1[2].x) * nd, (a0[2].y + a1[2].y) * nd,
                            (a0[3].x + a1[3].x) * nd, (a0[3].y + a1[3].y) * nd);
    float4* out = reinterpret_cast<float4*>(g_bufB) + (size_t)node * 16 + q * 2;
    out[0] = lo;
    out[1] = hi;
}

// ---------------- GEMM (fp32 in g_bufB; OUT16 -> g_h16 fp16 *norm_src, else -> g_bufA fp32) ----
template<bool OUT16>
__global__ void __launch_bounds__(256) k_gemm(const float* __restrict__ W,
                                              const float* __restrict__ b, int N) {
    __shared__ float Ws[DN * DN];
    __shared__ float bs[DN];
    int tid = threadIdx.x;
    for (int i = tid; i < DN * DN; i += 256) Ws[i] = W[i];
    if (tid < DN) bs[tid] = b[tid];
    __syncthreads();

    int idx = tid >> 1, half = tid & 1;
    int n0 = blockIdx.x * 256 + idx;
    int n1 = n0 + 128;
    bool v0 = n0 < N, v1 = n1 < N;

    const float4* WsV = reinterpret_cast<const float4*>(Ws);
    const float4* a0 = reinterpret_cast<const float4*>(g_bufB + (size_t)n0 * DN);
    const float4* a1 = reinterpret_cast<const float4*>(g_bufB + (size_t)n1 * DN);
    int qb = half * 8;

    float acc0[32], acc1[32];
    #pragma unroll
    for (int j = 0; j < 32; j++) { acc0[j] = 0.f; acc1[j] = 0.f; }

    #pragma unroll
    for (int kk = 0; kk < 16; kk++) {
        float4 A0 = v0 ? a0[kk] : make_float4(0.f, 0.f, 0.f, 0.f);
        float4 A1 = v1 ? a1[kk] : make_float4(0.f, 0.f, 0.f, 0.f);
        #pragma unroll
        for (int r = 0; r < 4; r++) {
            int k = kk * 4 + r;
            float x0 = (r == 0) ? A0.x : (r == 1) ? A0.y : (r == 2) ? A0.z : A0.w;
            float x1 = (r == 0) ? A1.x : (r == 1) ? A1.y : (r == 2) ? A1.z : A1.w;
            #pragma unroll
            for (int q = 0; q < 8; q++) {
                float4 w = WsV[k * 16 + qb + q];
                acc0[q * 4 + 0] += x0 * w.x; acc0[q * 4 + 1] += x0 * w.y;
                acc0[q * 4 + 2] += x0 * w.z; acc0[q * 4 + 3] += x0 * w.w;
                acc1[q * 4 + 0] += x1 * w.x; acc1[q * 4 + 1] += x1 * w.y;
                acc1[q * 4 + 2] += x1 * w.z; acc1[q * 4 + 3] += x1 * w.w;
            }
        }
    }

    #pragma unroll
    for (int which = 0; which < 2; which++) {
        int n = which ? n1 : n0;
        if (which ? !v1 : !v0) continue;
        float* acc = which ? acc1 : acc0;
        if (OUT16) {
            float ns = g_norm[n];
            uint4* dst16 = reinterpret_cast<uint4*>(g_h16 + (size_t)n * DN + half * 32);
            #pragma unroll
            for (int u = 0; u < 4; u++) {
                int j = u * 8;
                uint4 pk;
                pk.x = f2h(fmaxf(acc[j + 0] + bs[half * 32 + j + 0], 0.f) * ns,
                           fmaxf(acc[j + 1] + bs[half * 32 + j + 1], 0.f) * ns);
                pk.y = f2h(fmaxf(acc[j + 2] + bs[half * 32 + j + 2], 0.f) * ns,
                           fmaxf(acc[j + 3] + bs[half * 32 + j + 3], 0.f) * ns);
                pk.z = f2h(fmaxf(acc[j + 4] + bs[half * 32 + j + 4], 0.f) * ns,
                           fmaxf(acc[j + 5] + bs[half * 32 + j + 5], 0.f) * ns);
                pk.w = f2h(fmaxf(acc[j + 6] + bs[half * 32 + j + 6], 0.f) * ns,
                           fmaxf(acc[j + 7] + bs[half * 32 + j + 7], 0.f) * ns);
                dst16[u] = pk;
            }
        } else {
            float4* o4 = reinterpret_cast<float4*>(g_bufA + (size_t)n * DN + half * 32);
            #pragma unroll
            for (int qq = 0; qq < 8; qq++) {
                o4[qq] = make_float4(
                    fmaxf(acc[qq * 4 + 0] + bs[half * 32 + qq * 4 + 0], 0.f),
                    fmaxf(acc[qq * 4 + 1] + bs[half * 32 + qq * 4 + 1], 0.f),
                    fmaxf(acc[qq * 4 + 2] + bs[half * 32 + qq * 4 + 2], 0.f),
                    fmaxf(acc[qq * 4 + 3] + bs[half * 32 + qq * 4 + 3], 0.f));
            }
        }
    }
}

// ---------------- per-graph mean pool: 16 node-lanes x 16 float4-columns ----------------
#define PCH 256
__global__ void __launch_bounds__(256) k_pool(const int* __restrict__ gid, int N) {
    int t = threadIdx.x;
    int c4 = t & 15;
    int r  = t >> 4;
    int n0 = blockIdx.x * PCH;
    int nEnd = min(n0 + PCH, N);
    const float4* X = reinterpret_cast<const float4*>(g_bufA);

    float4 acc = make_float4(0.f, 0.f, 0.f, 0.f);
    float cnt = 0.f;
    int cur = -1;
    for (int n = n0 + r; n < nEnd; n += 16) {
        int g = __ldg(&gid[n]);
        if (g != cur) {
            if (cur >= 0) {
                float* p = &g_pooled[cur * DN + c4 * 4];
                atomicAdd(p + 0, acc.x); atomicAdd(p + 1, acc.y);
                atomicAdd(p + 2, acc.z); atomicAdd(p + 3, acc.w);
                if (c4 == 0) atomicAdd(&g_counts[cur], cnt);
                acc = make_float4(0.f, 0.f, 0.f, 0.f);
                cnt = 0.f;
            }
            cur = g;
        }
        float4 v = X[(size_t)n * 16 + c4];
        acc.x += v.x; acc.y += v.y; acc.z += v.z; acc.w += v.w;
        cnt += 1.f;
    }
    if (cur >= 0) {
        float* p = &g_pooled[cur * DN + c4 * 4];
        atomicAdd(p + 0, acc.x); atomicAdd(p + 1, acc.y);
        atomicAdd(p + 2, acc.z); atomicAdd(p + 3, acc.w);
        if (c4 == 0) atomicAdd(&g_counts[cur], cnt);
    }
}

// ---------------- classifier ----------------
__global__ void k_classify(const float* __restrict__ Wc, const float* __restrict__ bc,
                           float* __restrict__ out) {
    int g = blockIdx.x;
    int k = threadIdx.x;
    __shared__ float row[DN];
    if (k < DN) row[k] = g_pooled[g * DN + k];
    __syncthreads();
    if (k < 10) {
        float sum = 0.f;
        #pragma unroll
        for (int i = 0; i < DN; i++) sum += row[i] * __ldg(&Wc[i * 10 + k]);
        out[g * 10 + k] = sum / fmaxf(g_counts[g], 1.f) + __ldg(&bc[k]);
    }
}

// ---------------- launch ----------------
extern "C" void kernel_launch(void* const* d_in, const int* in_sizes, int n_in,
                              void* d_out, int out_size) {
    const float* h  = (const float*)d_in[0];
    const float* W1 = (const float*)d_in[1];
    const float* b1 = (const float*)d_in[2];
    const float* W2 = (const float*)d_in[3];
    const float* b2 = (const float*)d_in[4];
    const float* Wc = (const float*)d_in[5];
    const float* bc = (const float*)d_in[6];
    const int* src  = (const int*)d_in[7];
    const int* dst  = (const int*)d_in[8];
    const int* gid  = (const int*)d_in[9];
    float* out = (float*)d_out;

    const int N = in_sizes[9];          // 100000
    const int E = in_sizes[7];          // 1600000
    const int TPB = 256;
    const int G = (N + 1023) / 1024;

    // ---- CSR build ----
    k_zero_init<<<(2 * N + TPB - 1) / TPB, TPB>>>(N);
    k_degree<<<(E + TPB - 1) / TPB, TPB>>>(src, dst, E, N);
    k_scanA<<<G, 1024>>>(N);
    k_scanC<<<(N + 255) / 256, 256>>>(N, G);
    k_prep16<<<(N * 16 + TPB - 1) / TPB, TPB>>>((const float4*)h, N);
    k_fill<<<(E + TPB - 1) / TPB, TPB>>>(src, dst, E);

    // ---- layer 1: gather(g_h16 = prepped h) -> g_bufB; gemm -> g_h16 (fp16, *norm_src) ----
    k_gather16<<<(N * 8 + TPB - 1) / TPB, TPB>>>(N);
    k_gemm<true><<<(N + 255) / 256, 256>>>(W1, b1, N);

    // ---- layer 2: gather(g_h16 = h1) -> g_bufB; gemm -> g_bufA (fp32) ----
    k_gather16<<<(N * 8 + TPB - 1) / TPB, TPB>>>(N);
    k_gemm<false><<<(N + 255) / 256, 256>>>(W2, b2, N);

    // ---- pool + classify ----
    k_pool<<<(N + PCH - 1) / PCH, 256>>>(gid, N);
    k_classify<<<NGR, DN>>>(Wc, bc, out);
}